// round 5
// baseline (speedup 1.0000x reference)
#include <cuda_runtime.h>

#define BB 4096
#define NN 8192
#define DD 512
#define RR 4

__device__ float g_rnorm[NN];
__device__ float g_nll[NN];

__device__ __forceinline__ const float4* row_ptr4(const float* zi, const float* zj, int r) {
    const float* p = (r < BB) ? (zi + (size_t)r * DD) : (zj + (size_t)(r - BB) * DD);
    return reinterpret_cast<const float4*>(p);
}

// Kernel 1: per-row inverse norms. One warp per row, 4 float4 per lane.
__global__ void norms_kernel(const float* __restrict__ zi, const float* __restrict__ zj) {
    int warp = (blockIdx.x * blockDim.x + threadIdx.x) >> 5;
    int lane = threadIdx.x & 31;
    if (warp >= NN) return;
    const float4* p = row_ptr4(zi, zj, warp);
    float s = 0.0f;
#pragma unroll
    for (int k = 0; k < 4; k++) {
        float4 v = p[lane + 32 * k];
        s += v.x * v.x + v.y * v.y + v.z * v.z + v.w * v.w;
    }
#pragma unroll
    for (int o = 16; o; o >>= 1) s += __shfl_xor_sync(0xFFFFFFFFu, s, o);
    if (lane == 0) g_rnorm[warp] = 1.0f / fmaxf(sqrtf(s), 1e-8f);
}

// Kernel 2: per-row 5 dot products (1 positive + 4 negatives) + per-row NLL.
// One warp per row; row i held in registers, partners gathered (L2-resident).
__global__ void logits_kernel(const float* __restrict__ zi, const float* __restrict__ zj,
                              const int* __restrict__ neg_idx) {
    int row = (blockIdx.x * blockDim.x + threadIdx.x) >> 5;
    int lane = threadIdx.x & 31;
    if (row >= NN) return;

    const float4* pi = row_ptr4(zi, zj, row);
    float4 x[4];
#pragma unroll
    for (int k = 0; k < 4; k++) x[k] = pi[lane + 32 * k];

    int part[5];
    part[0] = (row + BB) & (NN - 1);
#pragma unroll
    for (int r = 0; r < RR; r++) {
        int v = neg_idx[row * RR + r];
        part[r + 1] = v + (v >= row ? 1 : 0);
    }

    float dots[5];
#pragma unroll
    for (int p = 0; p < 5; p++) {
        const float4* pj = row_ptr4(zi, zj, part[p]);
        float4 y0 = pj[lane];
        float4 y1 = pj[lane + 32];
        float4 y2 = pj[lane + 64];
        float4 y3 = pj[lane + 96];
        float acc = 0.0f;
        acc += x[0].x * y0.x + x[0].y * y0.y + x[0].z * y0.z + x[0].w * y0.w;
        acc += x[1].x * y1.x + x[1].y * y1.y + x[1].z * y1.z + x[1].w * y1.w;
        acc += x[2].x * y2.x + x[2].y * y2.y + x[2].z * y2.z + x[2].w * y2.w;
        acc += x[3].x * y3.x + x[3].y * y3.y + x[3].z * y3.z + x[3].w * y3.w;
        dots[p] = acc;
    }
#pragma unroll
    for (int p = 0; p < 5; p++) {
#pragma unroll
        for (int o = 16; o; o >>= 1) dots[p] += __shfl_xor_sync(0xFFFFFFFFu, dots[p], o);
    }

    if (lane == 0) {
        const float invT = 1.0f / (0.5f + 1e-8f);
        float si = g_rnorm[row];
        float l[5];
#pragma unroll
        for (int p = 0; p < 5; p++) l[p] = dots[p] * si * g_rnorm[part[p]] * invT;
        float m = l[0];
#pragma unroll
        for (int p = 1; p < 5; p++) m = fmaxf(m, l[p]);
        float se = 0.0f;
#pragma unroll
        for (int p = 0; p < 5; p++) se += expf(l[p] - m);
        g_nll[row] = m + logf(se) - l[0];
    }
}

// Kernel 3: deterministic reduce of 8192 NLLs -> mean, single block.
__global__ void reduce_kernel(float* __restrict__ out) {
    __shared__ float warp_sums[32];
    int tid = threadIdx.x;            // 1024 threads
    float s = 0.0f;
#pragma unroll
    for (int k = 0; k < NN / 1024; k++) s += g_nll[tid + k * 1024];
#pragma unroll
    for (int o = 16; o; o >>= 1) s += __shfl_xor_sync(0xFFFFFFFFu, s, o);
    if ((tid & 31) == 0) warp_sums[tid >> 5] = s;
    __syncthreads();
    if (tid < 32) {
        float t = warp_sums[tid];
#pragma unroll
        for (int o = 16; o; o >>= 1) t += __shfl_xor_sync(0xFFFFFFFFu, t, o);
        if (tid == 0) out[0] = t * (1.0f / (float)NN);
    }
}

extern "C" void kernel_launch(void* const* d_in, const int* in_sizes, int n_in,
                              void* d_out, int out_size) {
    const float* zi      = (const float*)d_in[0];
    const float* zj      = (const float*)d_in[1];
    const int*   neg_idx = (const int*)d_in[2];
    float* out = (float*)d_out;

    // 1 warp per row, 128-thread blocks => 4 rows/block => 2048 blocks
    norms_kernel<<<NN / 4, 128>>>(zi, zj);
    logits_kernel<<<NN / 4, 128>>>(zi, zj, neg_idx);
    reduce_kernel<<<1, 1024>>>(out);
}

// round 6
// speedup vs baseline: 1.1552x; 1.1552x over previous
#include <cuda_runtime.h>

#define BB 4096
#define NN 8192
#define DD 512
#define RR 4

__device__ float g_nll[NN];

__device__ __forceinline__ const float4* row_ptr4(const float* zi, const float* zj, int r) {
    const float* p = (r < BB) ? (zi + (size_t)r * DD) : (zj + (size_t)(r - BB) * DD);
    return reinterpret_cast<const float4*>(p);
}

// Fused kernel: one warp per row. Loads row x + 5 partner rows, computes
// x.x, x.y[p], y[p].y[p] in one pass (norms fused into the dot pass),
// then the per-row NLL. No separate norms pass, no rnorm table.
__global__ void __launch_bounds__(128) fused_kernel(const float* __restrict__ zi,
                                                    const float* __restrict__ zj,
                                                    const int* __restrict__ neg_idx) {
    int row  = (blockIdx.x * blockDim.x + threadIdx.x) >> 5;
    int lane = threadIdx.x & 31;
    if (row >= NN) return;

    // Row x: 16 floats/lane as 4x float4
    const float4* pi = row_ptr4(zi, zj, row);
    float4 x[4];
#pragma unroll
    for (int k = 0; k < 4; k++) x[k] = pi[lane + 32 * k];

    // Partner indices (uniform across warp)
    int4 nv = *reinterpret_cast<const int4*>(neg_idx + row * RR);
    int part[5];
    part[0] = (row + BB) & (NN - 1);
    part[1] = nv.x + (nv.x >= row ? 1 : 0);
    part[2] = nv.y + (nv.y >= row ? 1 : 0);
    part[3] = nv.z + (nv.z >= row ? 1 : 0);
    part[4] = nv.w + (nv.w >= row ? 1 : 0);

    // Front-load ALL partner data: 20 independent LDG.128 in flight
    float4 y[5][4];
#pragma unroll
    for (int p = 0; p < 5; p++) {
        const float4* pj = row_ptr4(zi, zj, part[p]);
#pragma unroll
        for (int k = 0; k < 4; k++) y[p][k] = pj[lane + 32 * k];
    }

    // x.x, and per-partner x.y / y.y
    float x2 = 0.0f;
#pragma unroll
    for (int k = 0; k < 4; k++)
        x2 += x[k].x * x[k].x + x[k].y * x[k].y + x[k].z * x[k].z + x[k].w * x[k].w;

    float dot[5], y2[5];
#pragma unroll
    for (int p = 0; p < 5; p++) {
        float d = 0.0f, n = 0.0f;
#pragma unroll
        for (int k = 0; k < 4; k++) {
            float4 a = x[k], b = y[p][k];
            d += a.x * b.x + a.y * b.y + a.z * b.z + a.w * b.w;
            n += b.x * b.x + b.y * b.y + b.z * b.z + b.w * b.w;
        }
        dot[p] = d;
        y2[p]  = n;
    }

    // Warp reductions (11 values)
#pragma unroll
    for (int o = 16; o; o >>= 1) {
        x2 += __shfl_xor_sync(0xFFFFFFFFu, x2, o);
#pragma unroll
        for (int p = 0; p < 5; p++) {
            dot[p] += __shfl_xor_sync(0xFFFFFFFFu, dot[p], o);
            y2[p]  += __shfl_xor_sync(0xFFFFFFFFu, y2[p], o);
        }
    }

    if (lane == 0) {
        const float invT = 1.0f / (0.5f + 1e-8f);
        float rnx = 1.0f / fmaxf(sqrtf(x2), 1e-8f);
        float l[5];
#pragma unroll
        for (int p = 0; p < 5; p++) {
            float rny = 1.0f / fmaxf(sqrtf(y2[p]), 1e-8f);
            l[p] = dot[p] * rnx * rny * invT;
        }
        float m = l[0];
#pragma unroll
        for (int p = 1; p < 5; p++) m = fmaxf(m, l[p]);
        float se = 0.0f;
#pragma unroll
        for (int p = 0; p < 5; p++) se += expf(l[p] - m);
        g_nll[row] = m + logf(se) - l[0];
    }
}

// Deterministic reduce of 8192 NLLs -> mean, single block.
__global__ void reduce_kernel(float* __restrict__ out) {
    __shared__ float warp_sums[32];
    int tid = threadIdx.x;            // 1024 threads
    float s = 0.0f;
#pragma unroll
    for (int k = 0; k < NN / 1024; k++) s += g_nll[tid + k * 1024];
#pragma unroll
    for (int o = 16; o; o >>= 1) s += __shfl_xor_sync(0xFFFFFFFFu, s, o);
    if ((tid & 31) == 0) warp_sums[tid >> 5] = s;
    __syncthreads();
    if (tid < 32) {
        float t = warp_sums[tid];
#pragma unroll
        for (int o = 16; o; o >>= 1) t += __shfl_xor_sync(0xFFFFFFFFu, t, o);
        if (tid == 0) out[0] = t * (1.0f / (float)NN);
    }
}

extern "C" void kernel_launch(void* const* d_in, const int* in_sizes, int n_in,
                              void* d_out, int out_size) {
    const float* zi      = (const float*)d_in[0];
    const float* zj      = (const float*)d_in[1];
    const int*   neg_idx = (const int*)d_in[2];
    float* out = (float*)d_out;

    fused_kernel<<<NN / 4, 128>>>(zi, zj, neg_idx);
    reduce_kernel<<<1, 1024>>>(out);
}